// round 11
// baseline (speedup 1.0000x reference)
#include <cuda_runtime.h>
#include <cuda_fp16.h>
#include <math.h>
#include <cstdint>

// Problem constants
#define Bsz 2
#define Tq  2048
#define Dm  1024
#define Hh  16
#define DH  64

// ---------------------------------------------------------------------------
// Scratch (allocation-free rule: __device__ globals)
// ---------------------------------------------------------------------------
__device__ float g_q [Bsz * Tq * Dm];
__device__ float g_k [Bsz * Tq * Dm];
__device__ float g_v [Bsz * Tq * Dm];
__device__ float g_ao[Bsz * Tq * Dm];

// ---------------------------------------------------------------------------
// Helpers
// ---------------------------------------------------------------------------
__device__ __forceinline__ uint32_t smem_to_u32(const void* p) {
    uint32_t a;
    asm("{ .reg .u64 t; cvta.to.shared.u64 t, %1; cvt.u32.u64 %0, t; }"
        : "=r"(a) : "l"(p));
    return a;
}
__device__ __forceinline__ uint32_t pack_h2(float x, float y) {
    __half2 h = __floats2half2_rn(x, y);
    return *reinterpret_cast<uint32_t*>(&h);
}
__device__ __forceinline__ void split_h2(float x, float y, uint32_t& hi, uint32_t& lo) {
    __half hx = __float2half_rn(x), hy = __float2half_rn(y);
    __half lx = __float2half_rn(x - __half2float(hx));
    __half ly = __float2half_rn(y - __half2float(hy));
    __half2 H = __halves2half2(hx, hy), L = __halves2half2(lx, ly);
    hi = *reinterpret_cast<uint32_t*>(&H);
    lo = *reinterpret_cast<uint32_t*>(&L);
}
__device__ __forceinline__ void mma_f16(float* c, const uint32_t* a,
                                        uint32_t b0, uint32_t b1)
{
    asm volatile(
        "mma.sync.aligned.m16n8k16.row.col.f32.f16.f16.f32 "
        "{%0,%1,%2,%3}, {%4,%5,%6,%7}, {%8,%9}, {%0,%1,%2,%3};"
        : "+f"(c[0]), "+f"(c[1]), "+f"(c[2]), "+f"(c[3])
        : "r"(a[0]), "r"(a[1]), "r"(a[2]), "r"(a[3]), "r"(b0), "r"(b1));
}
#define LDMATRIX_X4(r0, r1, r2, r3, addr) \
    asm volatile("ldmatrix.sync.aligned.m8n8.x4.shared.b16 {%0,%1,%2,%3}, [%4];" \
                 : "=r"(r0), "=r"(r1), "=r"(r2), "=r"(r3) : "r"(addr))
#define LDMATRIX_X4_T(r0, r1, r2, r3, addr) \
    asm volatile("ldmatrix.sync.aligned.m8n8.x4.trans.shared.b16 {%0,%1,%2,%3}, [%4];" \
                 : "=r"(r0), "=r"(r1), "=r"(r2), "=r"(r3) : "r"(addr))

// ---------------------------------------------------------------------------
// fp16 GEMM, ldmatrix edition. C = A[4096,1024] @ W[1024,1024].
// CTA 128x128, BK=32, 8 warps (warp 32x64), double-buffered smem.
// A smem: [128 rows][144B stride] (16-aligned; phase banks 36r->4r mod 32).
// B smem: [32 k-rows][272B stride] (FIX: 272 = 17*16, 16-byte aligned for
//         ldmatrix.trans; per-phase banks 68k -> 4k mod 32, conflict-free.
//         R10's 264B stride faulted: 264 mod 16 = 8 -> misaligned address.)
// Fused QKV: blockIdx.z selects (W, C).
// ---------------------------------------------------------------------------
#define GM_BK 32
#define GA_BYTES (128 * 144)             // 18432
#define GB_STRIDE 272
#define GB_BYTES (32 * GB_STRIDE)        // 8704
#define GSA0 0
#define GSB0 GA_BYTES
#define GSA1 (GSB0 + GB_BYTES)           // 27136
#define GSB1 (GSA1 + GA_BYTES)           // 45568
#define SMEM_GEMM (GSB1 + GB_BYTES)      // 54272

__global__ __launch_bounds__(256)
void gemm_mma(const float* __restrict__ A,
              const float* __restrict__ W0, const float* __restrict__ W1,
              const float* __restrict__ W2,
              float* __restrict__ C0, float* __restrict__ C1,
              float* __restrict__ C2)
{
    extern __shared__ char smem[];
    const uint32_t sb  = smem_to_u32(smem);
    const int tid  = threadIdx.x;
    const int lane = tid & 31;
    const int lrow = lane >> 2;
    const int lcol = lane & 3;
    const int wid  = tid >> 5;
    const int wm   = wid & 3;
    const int wn   = wid >> 2;
    const int bm   = blockIdx.y * 128;
    const int bn   = blockIdx.x * 128;
    const int z    = blockIdx.z;
    const float* W = (z == 0) ? W0 : (z == 1) ? W1 : W2;
    float*       C = (z == 0) ? C0 : (z == 1) ? C1 : C2;

    float acc[2][8][4];
#pragma unroll
    for (int i = 0; i < 2; i++)
#pragma unroll
        for (int j = 0; j < 8; j++)
#pragma unroll
            for (int q = 0; q < 4; q++) acc[i][j][q] = 0.f;

    float4 stA[4], stB[4];

    auto LDG = [&](int k0) {
#pragma unroll
        for (int it = 0; it < 4; it++) {
            int i = tid + it * 256;                // 128 rows x 8 float4
            stA[it] = *(const float4*)(A + (size_t)(bm + (i >> 3)) * Dm + k0 + (i & 7) * 4);
        }
#pragma unroll
        for (int it = 0; it < 4; it++) {
            int i = tid + it * 256;                // 32 k x 32 float4
            stB[it] = *(const float4*)(W + (size_t)(k0 + (i >> 5)) * Dm + bn + (i & 31) * 4);
        }
    };

    auto STS = [&](uint32_t sa, uint32_t sbb) {
#pragma unroll
        for (int it = 0; it < 4; it++) {
            int i = tid + it * 256;
            int r = i >> 3, c4 = i & 7;
            uint32_t ad = sa + (uint32_t)(r * 144 + c4 * 8);
            asm volatile("st.shared.v2.b32 [%0], {%1,%2};" :: "r"(ad),
                "r"(pack_h2(stA[it].x, stA[it].y)),
                "r"(pack_h2(stA[it].z, stA[it].w)) : "memory");
        }
#pragma unroll
        for (int it = 0; it < 4; it++) {
            int i = tid + it * 256;
            int k = i >> 5, n4 = i & 31;
            uint32_t ad = sbb + (uint32_t)(k * GB_STRIDE + n4 * 8);
            asm volatile("st.shared.v2.b32 [%0], {%1,%2};" :: "r"(ad),
                "r"(pack_h2(stB[it].x, stB[it].y)),
                "r"(pack_h2(stB[it].z, stB[it].w)) : "memory");
        }
    };

    auto COMPUTE = [&](uint32_t sa, uint32_t sbb) {
#pragma unroll
        for (int ks = 0; ks < 2; ks++) {
            uint32_t af[2][4];
#pragma unroll
            for (int i = 0; i < 2; i++) {
                uint32_t ad = sa + (uint32_t)((wm * 32 + i * 16 + (lane & 15)) * 144
                                              + (lane >> 4) * 16 + ks * 32);
                LDMATRIX_X4(af[i][0], af[i][1], af[i][2], af[i][3], ad);
            }
#pragma unroll
            for (int jp = 0; jp < 4; jp++) {
                uint32_t b0, b1, b2, b3;
                uint32_t ad = sbb
                    + (uint32_t)((ks * 16 + (lane & 7) + 8 * ((lane >> 3) & 1)) * GB_STRIDE
                                 + (wn * 64 + jp * 16 + (lane >> 4) * 8) * 2);
                LDMATRIX_X4_T(b0, b1, b2, b3, ad);
#pragma unroll
                for (int i = 0; i < 2; i++) {
                    mma_f16(acc[i][2 * jp],     af[i], b0, b1);
                    mma_f16(acc[i][2 * jp + 1], af[i], b2, b3);
                }
            }
        }
    };

    LDG(0);
    STS(sb + GSA0, sb + GSB0);
    __syncthreads();

#pragma unroll 1
    for (int ch = 0; ch < Dm / GM_BK; ch++) {
        const int p = ch & 1;
        if (ch + 1 < Dm / GM_BK) LDG((ch + 1) * GM_BK);
        COMPUTE(sb + (p ? GSA1 : GSA0), sb + (p ? GSB1 : GSB0));
        if (ch + 1 < Dm / GM_BK) STS(sb + (p ? GSA0 : GSA1), sb + (p ? GSB0 : GSB1));
        __syncthreads();
    }

#pragma unroll
    for (int i = 0; i < 2; i++) {
        int r0 = bm + wm * 32 + i * 16 + lrow;
#pragma unroll
        for (int j = 0; j < 8; j++) {
            int c = bn + wn * 64 + j * 8 + lcol * 2;
            *(float2*)(C + (size_t)r0 * Dm + c)       = make_float2(acc[i][j][0], acc[i][j][1]);
            *(float2*)(C + (size_t)(r0 + 8) * Dm + c) = make_float2(acc[i][j][2], acc[i][j][3]);
        }
    }
}

// ---------------------------------------------------------------------------
// Causal flash attention, fp16 mma + ldmatrix, P-in-registers, double-buffered
// K/V smem (ONE __syncthreads per ktile). Unchanged from R10 (its strides
// were already 16-aligned).
// smem:
//   AT_Q  = 0      Q stage fp32 [128][68] = 34816 (prologue only)
//   buf0: K hi 34816, K lo 44032, V 53248   (each 64 rows x 144B)
//   buf1: K hi 62464, K lo 71680, V 80896
// ---------------------------------------------------------------------------
#define AT_Q   0
#define AT_KB0 34816
#define AT_KB1 62464
#define KV_LO  9216
#define KV_V   18432
#define SMEM_ATTN 90112
#define KP_STRIDE 144

__global__ __launch_bounds__(256, 1)
void attn_mma(const float* __restrict__ Q, const float* __restrict__ K,
              const float* __restrict__ V, float* __restrict__ O)
{
    extern __shared__ char smem[];
    float* smf = (float*)smem;
    const uint32_t sb = smem_to_u32(smem);
    const int tid  = threadIdx.x;
    const int lane = tid & 31;
    const int lrow = lane >> 2;
    const int lcol = lane & 3;
    const int wid  = tid >> 5;
    const int qt   = blockIdx.x;
    const int bh   = blockIdx.y;
    const int b    = bh >> 4;
    const int h    = bh & 15;
    const int q0   = qt * 128;
    const size_t headoff = (size_t)b * Tq * Dm + (size_t)h * DH;

    const float scale = 0.125f * 1.44269504089f;  // 1/sqrt(64) * log2(e)

    // ---- Stage Q (scaled fp32), extract hi/lo fp16 fragments ----
    {
        const float* Qb = Q + headoff + (size_t)q0 * Dm;
#pragma unroll
        for (int t = 0; t < 8; t++) {
            int i = tid + t * 256;
            int r = i >> 4, c4 = i & 15;
            float4 v = *(const float4*)(Qb + (size_t)r * Dm + c4 * 4);
            v.x *= scale; v.y *= scale; v.z *= scale; v.w *= scale;
            *(float4*)&smf[r * 68 + c4 * 4] = v;
        }
    }
    __syncthreads();

    uint32_t qhi[4][4], qlo[4][4];
    {
        const int row = wid * 16 + lrow;
#pragma unroll
        for (int ks = 0; ks < 4; ks++) {
            int c = ks * 16 + lcol * 2;
            float2 f0 = *(float2*)&smf[row * 68 + c];
            float2 f1 = *(float2*)&smf[(row + 8) * 68 + c];
            float2 f2 = *(float2*)&smf[row * 68 + c + 8];
            float2 f3 = *(float2*)&smf[(row + 8) * 68 + c + 8];
            split_h2(f0.x, f0.y, qhi[ks][0], qlo[ks][0]);
            split_h2(f1.x, f1.y, qhi[ks][1], qlo[ks][1]);
            split_h2(f2.x, f2.y, qhi[ks][2], qlo[ks][2]);
            split_h2(f3.x, f3.y, qhi[ks][3], qlo[ks][3]);
        }
    }

    float m_i[2] = {-INFINITY, -INFINITY};
    float l_i[2] = {0.f, 0.f};
    float oacc[8][4];
#pragma unroll
    for (int j = 0; j < 8; j++)
#pragma unroll
        for (int q = 0; q < 4; q++) oacc[j][q] = 0.f;

    const int kmax = 2 * qt + 1;
    float4 rK[4], rV[4];

    auto LDG_KV = [&](int kt) {
        const float* Kb = K + headoff + (size_t)(kt * 64) * Dm;
        const float* Vb = V + headoff + (size_t)(kt * 64) * Dm;
#pragma unroll
        for (int t = 0; t < 4; t++) {
            int i = tid + t * 256;
            int r = i >> 4, c4 = i & 15;
            rK[t] = *(const float4*)(Kb + (size_t)r * Dm + c4 * 4);
            rV[t] = *(const float4*)(Vb + (size_t)r * Dm + c4 * 4);
        }
    };

    auto STS_KV = [&](int pbuf) {
        const uint32_t kb = sb + (pbuf ? AT_KB1 : AT_KB0);
#pragma unroll
        for (int t = 0; t < 4; t++) {
            int i = tid + t * 256;
            int key = i >> 4, c4 = i & 15;
            uint32_t rad = (uint32_t)(key * KP_STRIDE + c4 * 8);
            uint32_t h01, l01, h23, l23;
            split_h2(rK[t].x, rK[t].y, h01, l01);
            split_h2(rK[t].z, rK[t].w, h23, l23);
            asm volatile("st.shared.v2.b32 [%0], {%1,%2};"
                         :: "r"(kb + rad), "r"(h01), "r"(h23) : "memory");
            asm volatile("st.shared.v2.b32 [%0], {%1,%2};"
                         :: "r"(kb + KV_LO + rad), "r"(l01), "r"(l23) : "memory");
            asm volatile("st.shared.v2.b32 [%0], {%1,%2};"
                         :: "r"(kb + KV_V + rad),
                            "r"(pack_h2(rV[t].x, rV[t].y)),
                            "r"(pack_h2(rV[t].z, rV[t].w)) : "memory");
        }
    };

    LDG_KV(0);
    STS_KV(0);
    __syncthreads();

#pragma unroll 1
    for (int kt = 0; kt <= kmax; kt++) {
        const int p = kt & 1;
        const uint32_t kb = sb + (p ? AT_KB1 : AT_KB0);

        if (kt < kmax) LDG_KV(kt + 1);

        // ---- S = Q K^T (compensated fp16; K frags via ldmatrix.x4) ----
        float sacc[8][4];
#pragma unroll
        for (int j = 0; j < 8; j++)
#pragma unroll
            for (int q = 0; q < 4; q++) sacc[j][q] = 0.f;

#pragma unroll
        for (int ks = 0; ks < 4; ks++) {
#pragma unroll
            for (int jp = 0; jp < 4; jp++) {
                uint32_t ad = kb + (uint32_t)((jp * 16 + (lane & 15)) * KP_STRIDE
                                              + (lane >> 4) * 16 + ks * 32);
                uint32_t h0, h1, h2r, h3, l0, l1, l2r, l3;
                LDMATRIX_X4(h0, h1, h2r, h3, ad);
                LDMATRIX_X4(l0, l1, l2r, l3, ad + KV_LO);
                mma_f16(sacc[2 * jp],     qhi[ks], h0, h2r);
                mma_f16(sacc[2 * jp],     qlo[ks], h0, h2r);
                mma_f16(sacc[2 * jp],     qhi[ks], l0, l2r);
                mma_f16(sacc[2 * jp + 1], qhi[ks], h1, h3);
                mma_f16(sacc[2 * jp + 1], qlo[ks], h1, h3);
                mma_f16(sacc[2 * jp + 1], qhi[ks], l1, l3);
            }
        }

        // ---- Causal mask (diagonal-straddling ktiles only) ----
        if (kt >= 2 * qt) {
            int rowg0 = q0 + wid * 16 + lrow;
            int colg0 = kt * 64 + lcol * 2;
#pragma unroll
            for (int j = 0; j < 8; j++) {
                int c0 = colg0 + j * 8;
                if (c0     > rowg0)     sacc[j][0] = -INFINITY;
                if (c0 + 1 > rowg0)     sacc[j][1] = -INFINITY;
                if (c0     > rowg0 + 8) sacc[j][2] = -INFINITY;
                if (c0 + 1 > rowg0 + 8) sacc[j][3] = -INFINITY;
            }
        }

        // ---- Online softmax (base-2); P stays in sacc (registers) ----
#pragma unroll
        for (int h2 = 0; h2 < 2; h2++) {
            const int co = h2 * 2;
            float rmax = -INFINITY;
#pragma unroll
            for (int j = 0; j < 8; j++)
                rmax = fmaxf(rmax, fmaxf(sacc[j][co], sacc[j][co + 1]));
            rmax = fmaxf(rmax, __shfl_xor_sync(0xffffffffu, rmax, 1));
            rmax = fmaxf(rmax, __shfl_xor_sync(0xffffffffu, rmax, 2));

            float mnew = fmaxf(m_i[h2], rmax);
            float sc = exp2f(m_i[h2] - mnew);
            m_i[h2] = mnew;

            float rsum = 0.f;
#pragma unroll
            for (int j = 0; j < 8; j++) {
                float p0 = exp2f(sacc[j][co]     - mnew);
                float p1 = exp2f(sacc[j][co + 1] - mnew);
                sacc[j][co] = p0; sacc[j][co + 1] = p1;
                rsum += p0 + p1;
                oacc[j][co]     *= sc;
                oacc[j][co + 1] *= sc;
            }
            rsum += __shfl_xor_sync(0xffffffffu, rsum, 1);
            rsum += __shfl_xor_sync(0xffffffffu, rsum, 2);
            l_i[h2] = l_i[h2] * sc + rsum;
        }

        // ---- O += P @ V  (P C-frag == A-frag identity; V via ldmatrix.trans)
#pragma unroll
        for (int ks = 0; ks < 4; ks++) {
            uint32_t pa[4];
            pa[0] = pack_h2(sacc[2 * ks][0],     sacc[2 * ks][1]);
            pa[1] = pack_h2(sacc[2 * ks][2],     sacc[2 * ks][3]);
            pa[2] = pack_h2(sacc[2 * ks + 1][0], sacc[2 * ks + 1][1]);
            pa[3] = pack_h2(sacc[2 * ks + 1][2], sacc[2 * ks + 1][3]);
#pragma unroll
            for (int jp = 0; jp < 4; jp++) {
                uint32_t v0, v1, v2, v3;
                uint32_t ad = kb + KV_V
                    + (uint32_t)((ks * 16 + (lane & 7) + 8 * ((lane >> 3) & 1)) * KP_STRIDE
                                 + (jp * 16 + (lane >> 4) * 8) * 2);
                LDMATRIX_X4_T(v0, v1, v2, v3, ad);
                mma_f16(oacc[2 * jp],     pa, v0, v1);
                mma_f16(oacc[2 * jp + 1], pa, v2, v3);
            }
        }

        if (kt < kmax) STS_KV(p ^ 1);
        __syncthreads();
    }

    // ---- Epilogue ----
#pragma unroll
    for (int h2 = 0; h2 < 2; h2++) {
        float inv = 1.0f / l_i[h2];
        int rowg = q0 + wid * 16 + lrow + h2 * 8;
        float* Ob = O + headoff + (size_t)rowg * Dm;
        const int co = h2 * 2;
#pragma unroll
        for (int j = 0; j < 8; j++) {
            int c = j * 8 + lcol * 2;
            *(float2*)(Ob + c) = make_float2(oacc[j][co] * inv, oacc[j][co + 1] * inv);
        }
    }
}

// ---------------------------------------------------------------------------
// Launch.  Inputs: 0=x, 1=mask(unused), 2=Wq, 3=Wk, 4=Wv, 5=Wo
// ---------------------------------------------------------------------------
extern "C" void kernel_launch(void* const* d_in, const int* in_sizes, int n_in,
                              void* d_out, int out_size)
{
    const float* x  = (const float*)d_in[0];
    const float* Wq = (const float*)d_in[2];
    const float* Wk = (const float*)d_in[3];
    const float* Wv = (const float*)d_in[4];
    const float* Wo = (const float*)d_in[5];
    float* out = (float*)d_out;

    void *pq, *pk, *pv, *pao;
    cudaGetSymbolAddress(&pq,  g_q);
    cudaGetSymbolAddress(&pk,  g_k);
    cudaGetSymbolAddress(&pv,  g_v);
    cudaGetSymbolAddress(&pao, g_ao);

    cudaFuncSetAttribute(gemm_mma, cudaFuncAttributeMaxDynamicSharedMemorySize, SMEM_GEMM);
    cudaFuncSetAttribute(attn_mma, cudaFuncAttributeMaxDynamicSharedMemorySize, SMEM_ATTN);

    const int M = Bsz * Tq;                 // 4096
    dim3 gQKV(Dm / 128, M / 128, 3);        // (8, 32, 3) fused
    dim3 gO  (Dm / 128, M / 128, 1);
    dim3 gAttn(Tq / 128, Bsz * Hh);         // (16, 32)

    gemm_mma<<<gQKV, 256, SMEM_GEMM>>>(x, Wq, Wk, Wv,
                                       (float*)pq, (float*)pk, (float*)pv);

    attn_mma<<<gAttn, 256, SMEM_ATTN>>>((const float*)pq, (const float*)pk,
                                        (const float*)pv, (float*)pao);

    gemm_mma<<<gO, 256, SMEM_GEMM>>>((const float*)pao, Wo, Wo, Wo,
                                     out, out, out);
}

// round 14
// speedup vs baseline: 1.5266x; 1.5266x over previous
#include <cuda_runtime.h>
#include <cuda_fp16.h>
#include <math.h>
#include <cstdint>

// Problem constants
#define Bsz 2
#define Tq  2048
#define Dm  1024
#define Hh  16
#define DH  64

// ---------------------------------------------------------------------------
// Scratch (allocation-free rule: __device__ globals)
// ---------------------------------------------------------------------------
__device__ float g_q [Bsz * Tq * Dm];
__device__ float g_k [Bsz * Tq * Dm];
__device__ float g_v [Bsz * Tq * Dm];
__device__ float g_ao[Bsz * Tq * Dm];

// ---------------------------------------------------------------------------
// Helpers
// ---------------------------------------------------------------------------
__device__ __forceinline__ uint32_t smem_to_u32(const void* p) {
    uint32_t a;
    asm("{ .reg .u64 t; cvta.to.shared.u64 t, %1; cvt.u32.u64 %0, t; }"
        : "=r"(a) : "l"(p));
    return a;
}
__device__ __forceinline__ uint32_t pack_h2(float x, float y) {
    __half2 h = __floats2half2_rn(x, y);
    return *reinterpret_cast<uint32_t*>(&h);
}
__device__ __forceinline__ void split_h2(float x, float y, uint32_t& hi, uint32_t& lo) {
    __half hx = __float2half_rn(x), hy = __float2half_rn(y);
    __half lx = __float2half_rn(x - __half2float(hx));
    __half ly = __float2half_rn(y - __half2float(hy));
    __half2 H = __halves2half2(hx, hy), L = __halves2half2(lx, ly);
    hi = *reinterpret_cast<uint32_t*>(&H);
    lo = *reinterpret_cast<uint32_t*>(&L);
}
__device__ __forceinline__ void mma_f16(float* c, const uint32_t* a,
                                        uint32_t b0, uint32_t b1)
{
    asm volatile(
        "mma.sync.aligned.m16n8k16.row.col.f32.f16.f16.f32 "
        "{%0,%1,%2,%3}, {%4,%5,%6,%7}, {%8,%9}, {%0,%1,%2,%3};"
        : "+f"(c[0]), "+f"(c[1]), "+f"(c[2]), "+f"(c[3])
        : "r"(a[0]), "r"(a[1]), "r"(a[2]), "r"(a[3]), "r"(b0), "r"(b1));
}

// ---------------------------------------------------------------------------
// fp16 GEMM via mma.sync m16n8k16 (R9-proven inner loops; fused QKV via z).
// CTA 128x128, BK=32, 8 warps (warp 32x64), double-buffered.
// A smem: [128 rows][40 halves] (80B stride, 32 data halves/row)
// B smem: fragment-order [ntile(16)][kstep(2)][lane(32)][reg(2)] u32
// ---------------------------------------------------------------------------
#define GM_BK 32
#define GA_BYTES (128 * 80)
#define GB_BYTES (16 * 2 * 32 * 8)
#define GSA0 0
#define GSB0 GA_BYTES
#define GSA1 (GSB0 + GB_BYTES)
#define GSB1 (GSA1 + GA_BYTES)
#define SMEM_GEMM (GSB1 + GB_BYTES)      // 36864

__global__ __launch_bounds__(256)
void gemm_mma(const float* __restrict__ A,
              const float* __restrict__ W0, const float* __restrict__ W1,
              const float* __restrict__ W2,
              float* __restrict__ C0, float* __restrict__ C1,
              float* __restrict__ C2)
{
    extern __shared__ char smem[];
    const uint32_t sb  = smem_to_u32(smem);
    const int tid  = threadIdx.x;
    const int lane = tid & 31;
    const int lrow = lane >> 2;
    const int lcol = lane & 3;
    const int wid  = tid >> 5;
    const int wm   = wid & 3;
    const int wn   = wid >> 2;
    const int bm   = blockIdx.y * 128;
    const int bn   = blockIdx.x * 128;
    const int z    = blockIdx.z;
    const float* W = (z == 0) ? W0 : (z == 1) ? W1 : W2;
    float*       C = (z == 0) ? C0 : (z == 1) ? C1 : C2;

    float acc[2][8][4];
#pragma unroll
    for (int i = 0; i < 2; i++)
#pragma unroll
        for (int j = 0; j < 8; j++)
#pragma unroll
            for (int q = 0; q < 4; q++) acc[i][j][q] = 0.f;

    float4 stA[4], stB[4];

    auto LDG = [&](int k0) {
#pragma unroll
        for (int it = 0; it < 4; it++) {
            int i = tid + it * 256;
            stA[it] = *(const float4*)(A + (size_t)(bm + (i >> 3)) * Dm + k0 + (i & 7) * 4);
        }
#pragma unroll
        for (int it = 0; it < 4; it++) {
            int i = tid + it * 256;
            stB[it] = *(const float4*)(W + (size_t)(k0 + (i >> 5)) * Dm + bn + (i & 31) * 4);
        }
    };

    auto STS = [&](uint32_t sa, uint32_t sbb) {
#pragma unroll
        for (int it = 0; it < 4; it++) {
            int i = tid + it * 256;
            int r = i >> 3, c4 = i & 7;
            uint32_t ad = sa + (uint32_t)(r * 80 + c4 * 8);
            asm volatile("st.shared.v2.b32 [%0], {%1,%2};" :: "r"(ad),
                "r"(pack_h2(stA[it].x, stA[it].y)),
                "r"(pack_h2(stA[it].z, stA[it].w)) : "memory");
        }
#pragma unroll
        for (int it = 0; it < 4; it++) {
            int i = tid + it * 256;
            int k = i >> 5, n4 = i & 31;
            int kstep = k >> 4, kk = k & 15;
            int reg = kk >> 3, lc = (kk & 7) >> 1, hf = kk & 1;
            float vals[4] = {stB[it].x, stB[it].y, stB[it].z, stB[it].w};
#pragma unroll
            for (int e = 0; e < 4; e++) {
                int n = n4 * 4 + e;
                int ntile = n >> 3, nl = n & 7;
                int lanep = (nl * 4 + lc + ntile) & 31;
                uint32_t ad = sbb + (uint32_t)(((ntile * 2 + kstep) * 32 + lanep) * 8
                                               + reg * 4 + hf * 2);
                asm volatile("st.shared.b16 [%0], %1;"
                             :: "r"(ad), "h"(__half_as_ushort(__float2half_rn(vals[e])))
                             : "memory");
            }
        }
    };

    auto COMPUTE = [&](uint32_t sa, uint32_t sbb) {
#pragma unroll
        for (int ks = 0; ks < 2; ks++) {
            uint32_t af[2][4];
#pragma unroll
            for (int i = 0; i < 2; i++) {
                int row = wm * 32 + i * 16 + lrow;
                uint32_t base = sa + (uint32_t)(row * 80 + ks * 32 + lcol * 4);
                asm volatile("ld.shared.b32 %0, [%1];" : "=r"(af[i][0]) : "r"(base));
                asm volatile("ld.shared.b32 %0, [%1];" : "=r"(af[i][1]) : "r"(base + 640));
                asm volatile("ld.shared.b32 %0, [%1];" : "=r"(af[i][2]) : "r"(base + 16));
                asm volatile("ld.shared.b32 %0, [%1];" : "=r"(af[i][3]) : "r"(base + 656));
            }
            uint32_t bf[8][2];
#pragma unroll
            for (int j = 0; j < 8; j++) {
                int nt = wn * 8 + j;
                uint32_t ad = sbb + (uint32_t)(((nt * 2 + ks) * 32 + ((lane + nt) & 31)) * 8);
                asm volatile("ld.shared.v2.b32 {%0,%1}, [%2];"
                             : "=r"(bf[j][0]), "=r"(bf[j][1]) : "r"(ad));
            }
#pragma unroll
            for (int i = 0; i < 2; i++)
#pragma unroll
                for (int j = 0; j < 8; j++)
                    mma_f16(acc[i][j], af[i], bf[j][0], bf[j][1]);
        }
    };

    LDG(0);
    STS(sb + GSA0, sb + GSB0);
    __syncthreads();

#pragma unroll 1
    for (int ch = 0; ch < Dm / GM_BK; ch++) {
        const int p = ch & 1;
        if (ch + 1 < Dm / GM_BK) LDG((ch + 1) * GM_BK);
        COMPUTE(sb + (p ? GSA1 : GSA0), sb + (p ? GSB1 : GSB0));
        if (ch + 1 < Dm / GM_BK) STS(sb + (p ? GSA0 : GSA1), sb + (p ? GSB0 : GSB1));
        __syncthreads();
    }

#pragma unroll
    for (int i = 0; i < 2; i++) {
        int r0 = bm + wm * 32 + i * 16 + lrow;
#pragma unroll
        for (int j = 0; j < 8; j++) {
            int c = bn + wn * 64 + j * 8 + lcol * 2;
            *(float2*)(C + (size_t)r0 * Dm + c)       = make_float2(acc[i][j][0], acc[i][j][1]);
            *(float2*)(C + (size_t)(r0 + 8) * Dm + c) = make_float2(acc[i][j][2], acc[i][j][3]);
        }
    }
}

// ---------------------------------------------------------------------------
// Causal flash attention (R9-proven body). Only change: heavy-tile-first
// scheduling (qt = gridDim.x-1-blockIdx.x) so 17-ktile CTAs start in wave 1.
// smem bytes:
//   AT_P    0      Q stage fp32 [128][68] = 34816; reused as P [128 rows][144B]
//   AT_KHI  34816  K hi [64 rows][144B] = 9216
//   AT_KLO  44032  K lo [64 rows][144B] = 9216
//   AT_VF   53248  V frag-order [nt(8)][ks(4)][lane(32)][reg(2)] u32 = 8192
// ---------------------------------------------------------------------------
#define AT_P    0
#define AT_KHI  34816
#define AT_KLO  44032
#define AT_VF   53248
#define SMEM_ATTN 61440
#define KP_STRIDE 144

__global__ __launch_bounds__(256, 1)
void attn_mma(const float* __restrict__ Q, const float* __restrict__ K,
              const float* __restrict__ V, float* __restrict__ O)
{
    extern __shared__ char smem[];
    float* smf = (float*)smem;
    const uint32_t sb = smem_to_u32(smem);
    const int tid  = threadIdx.x;
    const int lane = tid & 31;
    const int lrow = lane >> 2;
    const int lcol = lane & 3;
    const int wid  = tid >> 5;
    const int qt   = (gridDim.x - 1) - blockIdx.x;   // heavy tiles first
    const int bh   = blockIdx.y;
    const int b    = bh >> 4;
    const int h    = bh & 15;
    const int q0   = qt * 128;
    const size_t headoff = (size_t)b * Tq * Dm + (size_t)h * DH;

    const float scale = 0.125f * 1.44269504089f;  // 1/sqrt(64) * log2(e)

    // ---- Stage Q (scaled, fp32) then build hi/lo fp16 fragments ----
    {
        const float* Qb = Q + headoff + (size_t)q0 * Dm;
#pragma unroll
        for (int t = 0; t < 8; t++) {
            int i = tid + t * 256;
            int r = i >> 4, c4 = i & 15;
            float4 v = *(const float4*)(Qb + (size_t)r * Dm + c4 * 4);
            v.x *= scale; v.y *= scale; v.z *= scale; v.w *= scale;
            *(float4*)&smf[r * 68 + c4 * 4] = v;
        }
    }
    __syncthreads();

    uint32_t qhi[4][4], qlo[4][4];
    {
        const int row = wid * 16 + lrow;
#pragma unroll
        for (int ks = 0; ks < 4; ks++) {
            int c = ks * 16 + lcol * 2;
            float2 f0 = *(float2*)&smf[row * 68 + c];
            float2 f1 = *(float2*)&smf[(row + 8) * 68 + c];
            float2 f2 = *(float2*)&smf[row * 68 + c + 8];
            float2 f3 = *(float2*)&smf[(row + 8) * 68 + c + 8];
            split_h2(f0.x, f0.y, qhi[ks][0], qlo[ks][0]);
            split_h2(f1.x, f1.y, qhi[ks][1], qlo[ks][1]);
            split_h2(f2.x, f2.y, qhi[ks][2], qlo[ks][2]);
            split_h2(f3.x, f3.y, qhi[ks][3], qlo[ks][3]);
        }
    }
    __syncthreads();   // Q staging region now free for P

    float m_i[2] = {-INFINITY, -INFINITY};
    float l_i[2] = {0.f, 0.f};
    float oacc[8][4];
#pragma unroll
    for (int j = 0; j < 8; j++)
#pragma unroll
        for (int q = 0; q < 4; q++) oacc[j][q] = 0.f;

    const int kmax = 2 * qt + 1;
    float4 rK[4], rV[4];

    auto LDG_KV = [&](int kt) {
        const float* Kb = K + headoff + (size_t)(kt * 64) * Dm;
        const float* Vb = V + headoff + (size_t)(kt * 64) * Dm;
#pragma unroll
        for (int t = 0; t < 4; t++) {
            int i = tid + t * 256;
            int r = i >> 4, c4 = i & 15;
            rK[t] = *(const float4*)(Kb + (size_t)r * Dm + c4 * 4);
            rV[t] = *(const float4*)(Vb + (size_t)r * Dm + c4 * 4);
        }
    };

    auto STS_KV = [&]() {
#pragma unroll
        for (int t = 0; t < 4; t++) {
            int i = tid + t * 256;
            int key = i >> 4, c4 = i & 15;
            float4 kv = rK[t];
            uint32_t h01, l01, h23, l23;
            split_h2(kv.x, kv.y, h01, l01);
            split_h2(kv.z, kv.w, h23, l23);
            uint32_t rad = (uint32_t)(key * KP_STRIDE + c4 * 8);
            asm volatile("st.shared.v2.b32 [%0], {%1,%2};"
                         :: "r"(sb + AT_KHI + rad), "r"(h01), "r"(h23) : "memory");
            asm volatile("st.shared.v2.b32 [%0], {%1,%2};"
                         :: "r"(sb + AT_KLO + rad), "r"(l01), "r"(l23) : "memory");
            int kstep = key >> 4, kk = key & 15;
            int reg = kk >> 3, lc = (kk & 7) >> 1, hf = kk & 1;
            float vv[4] = {rV[t].x, rV[t].y, rV[t].z, rV[t].w};
#pragma unroll
            for (int e = 0; e < 4; e++) {
                int dh = c4 * 4 + e;
                int ntile = dh >> 3, nl = dh & 7;
                int lanep = (nl * 4 + lc + ntile) & 31;
                uint32_t ad = sb + AT_VF + (uint32_t)(((ntile * 4 + kstep) * 32 + lanep) * 8
                                                      + reg * 4 + hf * 2);
                asm volatile("st.shared.b16 [%0], %1;"
                             :: "r"(ad), "h"(__half_as_ushort(__float2half_rn(vv[e])))
                             : "memory");
            }
        }
    };

    LDG_KV(0);
    STS_KV();
    __syncthreads();

#pragma unroll 1
    for (int kt = 0; kt <= kmax; kt++) {
        if (kt < kmax) LDG_KV(kt + 1);

        // ---- S = Q K^T (compensated fp16) ----
        float sacc[8][4];
#pragma unroll
        for (int j = 0; j < 8; j++)
#pragma unroll
            for (int q = 0; q < 4; q++) sacc[j][q] = 0.f;

#pragma unroll
        for (int ks = 0; ks < 4; ks++) {
#pragma unroll
            for (int j = 0; j < 8; j++) {
                uint32_t kb = sb + AT_KHI
                    + (uint32_t)((j * 8 + lrow) * KP_STRIDE + ks * 32 + lcol * 4);
                uint32_t kh0, kh1, kl0, kl1;
                asm volatile("ld.shared.b32 %0, [%1];" : "=r"(kh0) : "r"(kb));
                asm volatile("ld.shared.b32 %0, [%1];" : "=r"(kh1) : "r"(kb + 16));
                asm volatile("ld.shared.b32 %0, [%1];" : "=r"(kl0) : "r"(kb + (AT_KLO - AT_KHI)));
                asm volatile("ld.shared.b32 %0, [%1];" : "=r"(kl1) : "r"(kb + (AT_KLO - AT_KHI) + 16));
                mma_f16(sacc[j], qhi[ks], kh0, kh1);
                mma_f16(sacc[j], qlo[ks], kh0, kh1);
                mma_f16(sacc[j], qhi[ks], kl0, kl1);
            }
        }

        // ---- Causal mask (diagonal-straddling ktiles only) ----
        if (kt >= 2 * qt) {
            int rowg0 = q0 + wid * 16 + lrow;
            int colg0 = kt * 64 + lcol * 2;
#pragma unroll
            for (int j = 0; j < 8; j++) {
                int c0 = colg0 + j * 8;
                if (c0     > rowg0)     sacc[j][0] = -INFINITY;
                if (c0 + 1 > rowg0)     sacc[j][1] = -INFINITY;
                if (c0     > rowg0 + 8) sacc[j][2] = -INFINITY;
                if (c0 + 1 > rowg0 + 8) sacc[j][3] = -INFINITY;
            }
        }

        // ---- Online softmax (base-2); P -> smem as fp16 ----
#pragma unroll
        for (int h2 = 0; h2 < 2; h2++) {
            const int co = h2 * 2;
            float rmax = -INFINITY;
#pragma unroll
            for (int j = 0; j < 8; j++)
                rmax = fmaxf(rmax, fmaxf(sacc[j][co], sacc[j][co + 1]));
            rmax = fmaxf(rmax, __shfl_xor_sync(0xffffffffu, rmax, 1));
            rmax = fmaxf(rmax, __shfl_xor_sync(0xffffffffu, rmax, 2));

            float mnew = fmaxf(m_i[h2], rmax);
            float sc = exp2f(m_i[h2] - mnew);
            m_i[h2] = mnew;

            float rsum = 0.f;
            const int prow = wid * 16 + lrow + h2 * 8;
#pragma unroll
            for (int j = 0; j < 8; j++) {
                float p0 = exp2f(sacc[j][co]     - mnew);
                float p1 = exp2f(sacc[j][co + 1] - mnew);
                rsum += p0 + p1;
                uint32_t ad = sb + AT_P
                    + (uint32_t)(prow * KP_STRIDE + (j * 8 + lcol * 2) * 2);
                uint32_t pp = pack_h2(p0, p1);
                asm volatile("st.shared.b32 [%0], %1;" :: "r"(ad), "r"(pp) : "memory");
                oacc[j][co]     *= sc;
                oacc[j][co + 1] *= sc;
            }
            rsum += __shfl_xor_sync(0xffffffffu, rsum, 1);
            rsum += __shfl_xor_sync(0xffffffffu, rsum, 2);
            l_i[h2] = l_i[h2] * sc + rsum;
        }
        __syncwarp();

        // ---- O += P @ V (single fp16) ----
        {
            const int prow = wid * 16 + lrow;
#pragma unroll
            for (int ks = 0; ks < 4; ks++) {
                uint32_t pa[4];
                uint32_t pb = sb + AT_P + (uint32_t)(prow * KP_STRIDE + ks * 32 + lcol * 4);
                asm volatile("ld.shared.b32 %0, [%1];" : "=r"(pa[0]) : "r"(pb));
                asm volatile("ld.shared.b32 %0, [%1];" : "=r"(pa[1]) : "r"(pb + 8 * KP_STRIDE));
                asm volatile("ld.shared.b32 %0, [%1];" : "=r"(pa[2]) : "r"(pb + 16));
                asm volatile("ld.shared.b32 %0, [%1];" : "=r"(pa[3]) : "r"(pb + 8 * KP_STRIDE + 16));
#pragma unroll
                for (int j = 0; j < 8; j++) {
                    uint32_t v0, v1;
                    uint32_t ad = sb + AT_VF
                        + (uint32_t)(((j * 4 + ks) * 32 + ((lane + j) & 31)) * 8);
                    asm volatile("ld.shared.v2.b32 {%0,%1}, [%2];"
                                 : "=r"(v0), "=r"(v1) : "r"(ad));
                    mma_f16(oacc[j], pa, v0, v1);
                }
            }
        }
        __syncthreads();

        if (kt < kmax) {
            STS_KV();
            __syncthreads();
        }
    }

    // ---- Epilogue ----
#pragma unroll
    for (int h2 = 0; h2 < 2; h2++) {
        float inv = 1.0f / l_i[h2];
        int rowg = q0 + wid * 16 + lrow + h2 * 8;
        float* Ob = O + headoff + (size_t)rowg * Dm;
        const int co = h2 * 2;
#pragma unroll
        for (int j = 0; j < 8; j++) {
            int c = j * 8 + lcol * 2;
            *(float2*)(Ob + c) = make_float2(oacc[j][co] * inv, oacc[j][co + 1] * inv);
        }
    }
}

// ---------------------------------------------------------------------------
// Launch.  Inputs: 0=x, 1=mask(unused), 2=Wq, 3=Wk, 4=Wv, 5=Wo
// ---------------------------------------------------------------------------
extern "C" void kernel_launch(void* const* d_in, const int* in_sizes, int n_in,
                              void* d_out, int out_size)
{
    const float* x  = (const float*)d_in[0];
    const float* Wq = (const float*)d_in[2];
    const float* Wk = (const float*)d_in[3];
    const float* Wv = (const float*)d_in[4];
    const float* Wo = (const float*)d_in[5];
    float* out = (float*)d_out;

    void *pq, *pk, *pv, *pao;
    cudaGetSymbolAddress(&pq,  g_q);
    cudaGetSymbolAddress(&pk,  g_k);
    cudaGetSymbolAddress(&pv,  g_v);
    cudaGetSymbolAddress(&pao, g_ao);

    cudaFuncSetAttribute(gemm_mma, cudaFuncAttributeMaxDynamicSharedMemorySize, SMEM_GEMM);
    cudaFuncSetAttribute(attn_mma, cudaFuncAttributeMaxDynamicSharedMemorySize, SMEM_ATTN);

    const int M = Bsz * Tq;                 // 4096
    dim3 gQKV(Dm / 128, M / 128, 3);        // (8, 32, 3) fused QKV
    dim3 gO  (Dm / 128, M / 128, 1);
    dim3 gAttn(Tq / 128, Bsz * Hh);         // (16, 32)

    gemm_mma<<<gQKV, 256, SMEM_GEMM>>>(x, Wq, Wk, Wv,
                                       (float*)pq, (float*)pk, (float*)pv);

    attn_mma<<<gAttn, 256, SMEM_ATTN>>>((const float*)pq, (const float*)pk,
                                        (const float*)pv, (float*)pao);

    gemm_mma<<<gO, 256, SMEM_GEMM>>>((const float*)pao, Wo, Wo, Wo,
                                     out, out, out);
}

// round 17
// speedup vs baseline: 1.6430x; 1.0763x over previous
#include <cuda_runtime.h>
#include <cuda_fp16.h>
#include <math.h>
#include <cstdint>

// Problem constants
#define Bsz 2
#define Tq  2048
#define Dm  1024
#define Hh  16
#define DH  64

// ---------------------------------------------------------------------------
// Scratch (allocation-free rule: __device__ globals)
// ---------------------------------------------------------------------------
__device__ float  g_q  [Bsz * Tq * Dm];
__device__ float  g_k  [Bsz * Tq * Dm];
__device__ float  g_v  [Bsz * Tq * Dm];
__device__ __half g_xh [Bsz * Tq * Dm];   // x in fp16
__device__ __half g_aoh[Bsz * Tq * Dm];   // attention out in fp16
__device__ __half g_wqs[Dm * Dm];         // weights, fp16, fragment-order
__device__ __half g_wks[Dm * Dm];
__device__ __half g_wvs[Dm * Dm];
__device__ __half g_wos[Dm * Dm];

// ---------------------------------------------------------------------------
// Helpers
// ---------------------------------------------------------------------------
__device__ __forceinline__ uint32_t smem_to_u32(const void* p) {
    uint32_t a;
    asm("{ .reg .u64 t; cvta.to.shared.u64 t, %1; cvt.u32.u64 %0, t; }"
        : "=r"(a) : "l"(p));
    return a;
}
__device__ __forceinline__ uint32_t pack_h2(float x, float y) {
    __half2 h = __floats2half2_rn(x, y);
    return *reinterpret_cast<uint32_t*>(&h);
}
__device__ __forceinline__ void split_h2(float x, float y, uint32_t& hi, uint32_t& lo) {
    __half hx = __float2half_rn(x), hy = __float2half_rn(y);
    __half lx = __float2half_rn(x - __half2float(hx));
    __half ly = __float2half_rn(y - __half2float(hy));
    __half2 H = __halves2half2(hx, hy), L = __halves2half2(lx, ly);
    hi = *reinterpret_cast<uint32_t*>(&H);
    lo = *reinterpret_cast<uint32_t*>(&L);
}
__device__ __forceinline__ void mma_f16(float* c, const uint32_t* a,
                                        uint32_t b0, uint32_t b1)
{
    asm volatile(
        "mma.sync.aligned.m16n8k16.row.col.f32.f16.f16.f32 "
        "{%0,%1,%2,%3}, {%4,%5,%6,%7}, {%8,%9}, {%0,%1,%2,%3};"
        : "+f"(c[0]), "+f"(c[1]), "+f"(c[2]), "+f"(c[3])
        : "r"(a[0]), "r"(a[1]), "r"(a[2]), "r"(a[3]), "r"(b0), "r"(b1));
}
#define CP_ASYNC16(smem_ad, gptr) \
    asm volatile("cp.async.cg.shared.global [%0], [%1], 16;" \
                 :: "r"(smem_ad), "l"(gptr) : "memory")
#define CP_COMMIT() asm volatile("cp.async.commit_group;" ::: "memory")
#define CP_WAIT1()  asm volatile("cp.async.wait_group 1;" ::: "memory")
#define CP_WAIT0()  asm volatile("cp.async.wait_group 0;" ::: "memory")

// ---------------------------------------------------------------------------
// Prep kernels
// ---------------------------------------------------------------------------
// x fp32 -> fp16 (natural layout). 4M elems, 2 per thread.
__global__ __launch_bounds__(256)
void conv_x(const float* __restrict__ x, __half* __restrict__ xh)
{
    int i = blockIdx.x * 256 + threadIdx.x;
    float2 v = ((const float2*)x)[i];
    ((__half2*)xh)[i] = __floats2half2_rn(v.x, v.y);
}

// Weight fp32 [k][n] -> fp16 fragment-order tiles:
// out[(ntile128 * 32 + chunk) * 8192 bytes + R9-fragment-offset(k&31, n&127)]
__global__ __launch_bounds__(256)
void prep_w(const float* __restrict__ W0, const float* __restrict__ W1,
            const float* __restrict__ W2, const float* __restrict__ W3,
            __half* __restrict__ O0, __half* __restrict__ O1,
            __half* __restrict__ O2, __half* __restrict__ O3)
{
    const int z = blockIdx.z;
    const float* W = (z == 0) ? W0 : (z == 1) ? W1 : (z == 2) ? W2 : W3;
    __half*      O = (z == 0) ? O0 : (z == 1) ? O1 : (z == 2) ? O2 : O3;
    int idx = blockIdx.x * 256 + threadIdx.x;      // 1M elements
    int k_g = idx >> 10, n_g = idx & 1023;
    __half v = __float2half_rn(W[idx]);
    int t = n_g >> 7, n = n_g & 127, c = k_g >> 5, k = k_g & 31;
    int ntile = n >> 3, nl = n & 7;
    int kstep = k >> 4, kk = k & 15;
    int reg = kk >> 3, lc = (kk & 7) >> 1, hf = kk & 1;
    int lanep = (nl * 4 + lc + ntile) & 31;
    int off = ((ntile * 2 + kstep) * 32 + lanep) * 8 + reg * 4 + hf * 2;
    *(__half*)((char*)O + ((size_t)(t * 32 + c)) * 8192 + off) = v;
}

// ---------------------------------------------------------------------------
// fp16 GEMM: cp.async fill + R9-proven COMPUTE. C = A_h @ W (pre-scattered).
// CTA 128x128, BK=32, 8 warps, double-buffered. Fused QKV via z.
// A smem: [128 rows][80B stride] (64B data). B smem: 8192B fragment image.
// ---------------------------------------------------------------------------
#define GM_BK 32
#define GA_BYTES (128 * 80)              // 10240
#define GB_BYTES 8192
#define GSA0 0
#define GSB0 GA_BYTES
#define GSA1 (GSB0 + GB_BYTES)           // 18432
#define GSB1 (GSA1 + GA_BYTES)           // 28672
#define SMEM_GEMM (GSB1 + GB_BYTES)      // 36864

__global__ __launch_bounds__(256)
void gemm_mma(const __half* __restrict__ A_h,
              const __half* __restrict__ S0, const __half* __restrict__ S1,
              const __half* __restrict__ S2,
              float* __restrict__ C0, float* __restrict__ C1,
              float* __restrict__ C2)
{
    extern __shared__ char smem[];
    const uint32_t sb  = smem_to_u32(smem);
    const int tid  = threadIdx.x;
    const int lane = tid & 31;
    const int lrow = lane >> 2;
    const int lcol = lane & 3;
    const int wid  = tid >> 5;
    const int wm   = wid & 3;
    const int wn   = wid >> 2;
    const int bm   = blockIdx.y * 128;
    const int z    = blockIdx.z;
    const __half* Wsc = (z == 0) ? S0 : (z == 1) ? S1 : S2;
    float*        C   = (z == 0) ? C0 : (z == 1) ? C1 : C2;

    float acc[2][8][4];
#pragma unroll
    for (int i = 0; i < 2; i++)
#pragma unroll
        for (int j = 0; j < 8; j++)
#pragma unroll
            for (int q = 0; q < 4; q++) acc[i][j][q] = 0.f;

    // cp.async tile fill: A 2x16B + B 2x16B per thread
    auto CP_TILE = [&](int ch, int p) {
        const uint32_t sa  = sb + (p ? GSA1 : GSA0);
        const uint32_t sbb = sb + (p ? GSB1 : GSB0);
        const int k0 = ch * GM_BK;
#pragma unroll
        for (int t = 0; t < 2; t++) {
            int i = tid + t * 256;                 // 512: 128 rows x 4 segs
            int row = i >> 2, seg = i & 3;
            const __half* g = A_h + (size_t)(bm + row) * Dm + k0 + seg * 8;
            CP_ASYNC16(sa + (uint32_t)(row * 80 + seg * 16), g);
        }
        const __half* gw = Wsc + ((size_t)(blockIdx.x * 32 + ch)) * 4096;
#pragma unroll
        for (int t = 0; t < 2; t++) {
            int i = tid + t * 256;                 // 512 x 16B = 8192B
            CP_ASYNC16(sbb + (uint32_t)(i * 16), gw + i * 8);
        }
        CP_COMMIT();
    };

    auto COMPUTE = [&](uint32_t sa, uint32_t sbb) {
#pragma unroll
        for (int ks = 0; ks < 2; ks++) {
            uint32_t af[2][4];
#pragma unroll
            for (int i = 0; i < 2; i++) {
                int row = wm * 32 + i * 16 + lrow;
                uint32_t base = sa + (uint32_t)(row * 80 + ks * 32 + lcol * 4);
                asm volatile("ld.shared.b32 %0, [%1];" : "=r"(af[i][0]) : "r"(base));
                asm volatile("ld.shared.b32 %0, [%1];" : "=r"(af[i][1]) : "r"(base + 640));
                asm volatile("ld.shared.b32 %0, [%1];" : "=r"(af[i][2]) : "r"(base + 16));
                asm volatile("ld.shared.b32 %0, [%1];" : "=r"(af[i][3]) : "r"(base + 656));
            }
            uint32_t bf[8][2];
#pragma unroll
            for (int j = 0; j < 8; j++) {
                int nt = wn * 8 + j;
                uint32_t ad = sbb + (uint32_t)(((nt * 2 + ks) * 32 + ((lane + nt) & 31)) * 8);
                asm volatile("ld.shared.v2.b32 {%0,%1}, [%2];"
                             : "=r"(bf[j][0]), "=r"(bf[j][1]) : "r"(ad));
            }
#pragma unroll
            for (int i = 0; i < 2; i++)
#pragma unroll
                for (int j = 0; j < 8; j++)
                    mma_f16(acc[i][j], af[i], bf[j][0], bf[j][1]);
        }
    };

    CP_TILE(0, 0);

#pragma unroll 1
    for (int ch = 0; ch < Dm / GM_BK; ch++) {
        const int p = ch & 1;
        if (ch + 1 < Dm / GM_BK) {
            CP_TILE(ch + 1, p ^ 1);
            CP_WAIT1();
        } else {
            CP_WAIT0();
        }
        __syncthreads();
        COMPUTE(sb + (p ? GSA1 : GSA0), sb + (p ? GSB1 : GSB0));
        __syncthreads();
    }

#pragma unroll
    for (int i = 0; i < 2; i++) {
        int r0 = bm + wm * 32 + i * 16 + lrow;
#pragma unroll
        for (int j = 0; j < 8; j++) {
            int c = blockIdx.x * 128 + wn * 64 + j * 8 + lcol * 2;
            *(float2*)(C + (size_t)r0 * Dm + c)       = make_float2(acc[i][j][0], acc[i][j][1]);
            *(float2*)(C + (size_t)(r0 + 8) * Dm + c) = make_float2(acc[i][j][2], acc[i][j][3]);
        }
    }
}

// ---------------------------------------------------------------------------
// Causal flash attention (R14-proven body; heavy-tile-first). Only change:
// epilogue writes fp16 (the O-GEMM rounded it to fp16 anyway — same rounding).
// ---------------------------------------------------------------------------
#define AT_P    0
#define AT_KHI  34816
#define AT_KLO  44032
#define AT_VF   53248
#define SMEM_ATTN 61440
#define KP_STRIDE 144

__global__ __launch_bounds__(256, 1)
void attn_mma(const float* __restrict__ Q, const float* __restrict__ K,
              const float* __restrict__ V, __half* __restrict__ O)
{
    extern __shared__ char smem[];
    float* smf = (float*)smem;
    const uint32_t sb = smem_to_u32(smem);
    const int tid  = threadIdx.x;
    const int lane = tid & 31;
    const int lrow = lane >> 2;
    const int lcol = lane & 3;
    const int wid  = tid >> 5;
    const int qt   = (gridDim.x - 1) - blockIdx.x;   // heavy tiles first
    const int bh   = blockIdx.y;
    const int b    = bh >> 4;
    const int h    = bh & 15;
    const int q0   = qt * 128;
    const size_t headoff = (size_t)b * Tq * Dm + (size_t)h * DH;

    const float scale = 0.125f * 1.44269504089f;

    {
        const float* Qb = Q + headoff + (size_t)q0 * Dm;
#pragma unroll
        for (int t = 0; t < 8; t++) {
            int i = tid + t * 256;
            int r = i >> 4, c4 = i & 15;
            float4 v = *(const float4*)(Qb + (size_t)r * Dm + c4 * 4);
            v.x *= scale; v.y *= scale; v.z *= scale; v.w *= scale;
            *(float4*)&smf[r * 68 + c4 * 4] = v;
        }
    }
    __syncthreads();

    uint32_t qhi[4][4], qlo[4][4];
    {
        const int row = wid * 16 + lrow;
#pragma unroll
        for (int ks = 0; ks < 4; ks++) {
            int c = ks * 16 + lcol * 2;
            float2 f0 = *(float2*)&smf[row * 68 + c];
            float2 f1 = *(float2*)&smf[(row + 8) * 68 + c];
            float2 f2 = *(float2*)&smf[row * 68 + c + 8];
            float2 f3 = *(float2*)&smf[(row + 8) * 68 + c + 8];
            split_h2(f0.x, f0.y, qhi[ks][0], qlo[ks][0]);
            split_h2(f1.x, f1.y, qhi[ks][1], qlo[ks][1]);
            split_h2(f2.x, f2.y, qhi[ks][2], qlo[ks][2]);
            split_h2(f3.x, f3.y, qhi[ks][3], qlo[ks][3]);
        }
    }
    __syncthreads();

    float m_i[2] = {-INFINITY, -INFINITY};
    float l_i[2] = {0.f, 0.f};
    float oacc[8][4];
#pragma unroll
    for (int j = 0; j < 8; j++)
#pragma unroll
        for (int q = 0; q < 4; q++) oacc[j][q] = 0.f;

    const int kmax = 2 * qt + 1;
    float4 rK[4], rV[4];

    auto LDG_KV = [&](int kt) {
        const float* Kb = K + headoff + (size_t)(kt * 64) * Dm;
        const float* Vb = V + headoff + (size_t)(kt * 64) * Dm;
#pragma unroll
        for (int t = 0; t < 4; t++) {
            int i = tid + t * 256;
            int r = i >> 4, c4 = i & 15;
            rK[t] = *(const float4*)(Kb + (size_t)r * Dm + c4 * 4);
            rV[t] = *(const float4*)(Vb + (size_t)r * Dm + c4 * 4);
        }
    };

    auto STS_KV = [&]() {
#pragma unroll
        for (int t = 0; t < 4; t++) {
            int i = tid + t * 256;
            int key = i >> 4, c4 = i & 15;
            float4 kv = rK[t];
            uint32_t h01, l01, h23, l23;
            split_h2(kv.x, kv.y, h01, l01);
            split_h2(kv.z, kv.w, h23, l23);
            uint32_t rad = (uint32_t)(key * KP_STRIDE + c4 * 8);
            asm volatile("st.shared.v2.b32 [%0], {%1,%2};"
                         :: "r"(sb + AT_KHI + rad), "r"(h01), "r"(h23) : "memory");
            asm volatile("st.shared.v2.b32 [%0], {%1,%2};"
                         :: "r"(sb + AT_KLO + rad), "r"(l01), "r"(l23) : "memory");
            int kstep = key >> 4, kk = key & 15;
            int reg = kk >> 3, lc = (kk & 7) >> 1, hf = kk & 1;
            float vv[4] = {rV[t].x, rV[t].y, rV[t].z, rV[t].w};
#pragma unroll
            for (int e = 0; e < 4; e++) {
                int dh = c4 * 4 + e;
                int ntile = dh >> 3, nl = dh & 7;
                int lanep = (nl * 4 + lc + ntile) & 31;
                uint32_t ad = sb + AT_VF + (uint32_t)(((ntile * 4 + kstep) * 32 + lanep) * 8
                                                      + reg * 4 + hf * 2);
                asm volatile("st.shared.b16 [%0], %1;"
                             :: "r"(ad), "h"(__half_as_ushort(__float2half_rn(vv[e])))
                             : "memory");
            }
        }
    };

    LDG_KV(0);
    STS_KV();
    __syncthreads();

#pragma unroll 1
    for (int kt = 0; kt <= kmax; kt++) {
        if (kt < kmax) LDG_KV(kt + 1);

        float sacc[8][4];
#pragma unroll
        for (int j = 0; j < 8; j++)
#pragma unroll
            for (int q = 0; q < 4; q++) sacc[j][q] = 0.f;

#pragma unroll
        for (int ks = 0; ks < 4; ks++) {
#pragma unroll
            for (int j = 0; j < 8; j++) {
                uint32_t kb = sb + AT_KHI
                    + (uint32_t)((j * 8 + lrow) * KP_STRIDE + ks * 32 + lcol * 4);
                uint32_t kh0, kh1, kl0, kl1;
                asm volatile("ld.shared.b32 %0, [%1];" : "=r"(kh0) : "r"(kb));
                asm volatile("ld.shared.b32 %0, [%1];" : "=r"(kh1) : "r"(kb + 16));
                asm volatile("ld.shared.b32 %0, [%1];" : "=r"(kl0) : "r"(kb + (AT_KLO - AT_KHI)));
                asm volatile("ld.shared.b32 %0, [%1];" : "=r"(kl1) : "r"(kb + (AT_KLO - AT_KHI) + 16));
                mma_f16(sacc[j], qhi[ks], kh0, kh1);
                mma_f16(sacc[j], qlo[ks], kh0, kh1);
                mma_f16(sacc[j], qhi[ks], kl0, kl1);
            }
        }

        if (kt >= 2 * qt) {
            int rowg0 = q0 + wid * 16 + lrow;
            int colg0 = kt * 64 + lcol * 2;
#pragma unroll
            for (int j = 0; j < 8; j++) {
                int c0 = colg0 + j * 8;
                if (c0     > rowg0)     sacc[j][0] = -INFINITY;
                if (c0 + 1 > rowg0)     sacc[j][1] = -INFINITY;
                if (c0     > rowg0 + 8) sacc[j][2] = -INFINITY;
                if (c0 + 1 > rowg0 + 8) sacc[j][3] = -INFINITY;
            }
        }

#pragma unroll
        for (int h2 = 0; h2 < 2; h2++) {
            const int co = h2 * 2;
            float rmax = -INFINITY;
#pragma unroll
            for (int j = 0; j < 8; j++)
                rmax = fmaxf(rmax, fmaxf(sacc[j][co], sacc[j][co + 1]));
            rmax = fmaxf(rmax, __shfl_xor_sync(0xffffffffu, rmax, 1));
            rmax = fmaxf(rmax, __shfl_xor_sync(0xffffffffu, rmax, 2));

            float mnew = fmaxf(m_i[h2], rmax);
            float sc = exp2f(m_i[h2] - mnew);
            m_i[h2] = mnew;

            float rsum = 0.f;
            const int prow = wid * 16 + lrow + h2 * 8;
#pragma unroll
            for (int j = 0; j < 8; j++) {
                float p0 = exp2f(sacc[j][co]     - mnew);
                float p1 = exp2f(sacc[j][co + 1] - mnew);
                rsum += p0 + p1;
                uint32_t ad = sb + AT_P
                    + (uint32_t)(prow * KP_STRIDE + (j * 8 + lcol * 2) * 2);
                uint32_t pp = pack_h2(p0, p1);
                asm volatile("st.shared.b32 [%0], %1;" :: "r"(ad), "r"(pp) : "memory");
                oacc[j][co]     *= sc;
                oacc[j][co + 1] *= sc;
            }
            rsum += __shfl_xor_sync(0xffffffffu, rsum, 1);
            rsum += __shfl_xor_sync(0xffffffffu, rsum, 2);
            l_i[h2] = l_i[h2] * sc + rsum;
        }
        __syncwarp();

        {
            const int prow = wid * 16 + lrow;
#pragma unroll
            for (int ks = 0; ks < 4; ks++) {
                uint32_t pa[4];
                uint32_t pb = sb + AT_P + (uint32_t)(prow * KP_STRIDE + ks * 32 + lcol * 4);
                asm volatile("ld.shared.b32 %0, [%1];" : "=r"(pa[0]) : "r"(pb));
                asm volatile("ld.shared.b32 %0, [%1];" : "=r"(pa[1]) : "r"(pb + 8 * KP_STRIDE));
                asm volatile("ld.shared.b32 %0, [%1];" : "=r"(pa[2]) : "r"(pb + 16));
                asm volatile("ld.shared.b32 %0, [%1];" : "=r"(pa[3]) : "r"(pb + 8 * KP_STRIDE + 16));
#pragma unroll
                for (int j = 0; j < 8; j++) {
                    uint32_t v0, v1;
                    uint32_t ad = sb + AT_VF
                        + (uint32_t)(((j * 4 + ks) * 32 + ((lane + j) & 31)) * 8);
                    asm volatile("ld.shared.v2.b32 {%0,%1}, [%2];"
                                 : "=r"(v0), "=r"(v1) : "r"(ad));
                    mma_f16(oacc[j], pa, v0, v1);
                }
            }
        }
        __syncthreads();

        if (kt < kmax) {
            STS_KV();
            __syncthreads();
        }
    }

    // ---- Epilogue: write fp16 (single rounding, same as before-in-GEMM) ----
#pragma unroll
    for (int h2 = 0; h2 < 2; h2++) {
        float inv = 1.0f / l_i[h2];
        int rowg = q0 + wid * 16 + lrow + h2 * 8;
        __half* Ob = O + headoff + (size_t)rowg * Dm;
        const int co = h2 * 2;
#pragma unroll
        for (int j = 0; j < 8; j++) {
            int c = j * 8 + lcol * 2;
            *(__half2*)(Ob + c) = __floats2half2_rn(oacc[j][co] * inv, oacc[j][co + 1] * inv);
        }
    }
}

// ---------------------------------------------------------------------------
// Launch.  Inputs: 0=x, 1=mask(unused), 2=Wq, 3=Wk, 4=Wv, 5=Wo
// ---------------------------------------------------------------------------
extern "C" void kernel_launch(void* const* d_in, const int* in_sizes, int n_in,
                              void* d_out, int out_size)
{
    const float* x  = (const float*)d_in[0];
    const float* Wq = (const float*)d_in[2];
    const float* Wk = (const float*)d_in[3];
    const float* Wv = (const float*)d_in[4];
    const float* Wo = (const float*)d_in[5];
    float* out = (float*)d_out;

    void *pq, *pk, *pv, *pxh, *paoh, *pwqs, *pwks, *pwvs, *pwos;
    cudaGetSymbolAddress(&pq,   g_q);
    cudaGetSymbolAddress(&pk,   g_k);
    cudaGetSymbolAddress(&pv,   g_v);
    cudaGetSymbolAddress(&pxh,  g_xh);
    cudaGetSymbolAddress(&paoh, g_aoh);
    cudaGetSymbolAddress(&pwqs, g_wqs);
    cudaGetSymbolAddress(&pwks, g_wks);
    cudaGetSymbolAddress(&pwvs, g_wvs);
    cudaGetSymbolAddress(&pwos, g_wos);

    cudaFuncSetAttribute(gemm_mma, cudaFuncAttributeMaxDynamicSharedMemorySize, SMEM_GEMM);
    cudaFuncSetAttribute(attn_mma, cudaFuncAttributeMaxDynamicSharedMemorySize, SMEM_ATTN);

    const int M = Bsz * Tq;                 // 4096

    // Prep: x -> fp16; weights -> fp16 fragment-order
    conv_x<<<(M * Dm / 2) / 256, 256>>>(x, (__half*)pxh);
    dim3 gPrep(Dm * Dm / 256, 1, 4);
    prep_w<<<gPrep, 256>>>(Wq, Wk, Wv, Wo,
                           (__half*)pwqs, (__half*)pwks, (__half*)pwvs, (__half*)pwos);

    dim3 gQKV(Dm / 128, M / 128, 3);        // fused QKV
    dim3 gO  (Dm / 128, M / 128, 1);
    dim3 gAttn(Tq / 128, Bsz * Hh);

    gemm_mma<<<gQKV, 256, SMEM_GEMM>>>((const __half*)pxh,
                                       (const __half*)pwqs, (const __half*)pwks,
                                       (const __half*)pwvs,
                                       (float*)pq, (float*)pk, (float*)pv);

    attn_mma<<<gAttn, 256, SMEM_ATTN>>>((const float*)pq, (const float*)pk,
                                        (const float*)pv, (__half*)paoh);

    gemm_mma<<<gO, 256, SMEM_GEMM>>>((const __half*)paoh,
                                     (const __half*)pwos, (const __half*)pwos,
                                     (const __half*)pwos,
                                     out, out, out);
}